// round 1
// baseline (speedup 1.0000x reference)
#include <cuda_runtime.h>
#include <cstdint>

// Problem constants
#define BB  4
#define LL  4096
#define HID 1024
#define HH  16
#define DH  64
#define MM  128
#define BL  (BB*LL)          // 16384
#define EPS 1e-3f

// ---------------- scratch (static device globals; no allocation) -------------
__device__ float g_q  [(size_t)BL * HID];          // 64 MB   (also reused for att)
__device__ float g_k  [(size_t)BL * HID];          // 64 MB
__device__ float g_v  [(size_t)BL * HID];          // 64 MB
__device__ float g_qp [(size_t)BL * HH * MM];      // 128 MB
__device__ float g_kp [(size_t)BL * HH * MM];      // 128 MB
#define LSPLIT 16
__device__ float g_part[(size_t)BB * HH * LSPLIT * MM * 65];   // ~34 MB
__device__ float g_kvs [(size_t)BB * HH * MM * 65];            // ~2 MB

// ---------------- SGEMM: C[M,N] = A[M,K] * B[K,N], row-major, fp32 -----------
// BM=128, BN=128, BK=16, 256 threads, 8x8 per-thread microtile.
__global__ __launch_bounds__(256)
void sgemm_kernel(const float* __restrict__ A, const float* __restrict__ B,
                  float* __restrict__ C, int M, int N, int K)
{
    const int BM = 128, BN = 128, BK = 16, TM = 8, TN = 8;
    __shared__ float As[BK][BM];
    __shared__ float Bs[BK][BN];

    const int tid  = threadIdx.x;
    const int brow = blockIdx.y * BM;
    const int bcol = blockIdx.x * BN;
    const int tx = tid % (BN / TN);   // 0..15
    const int ty = tid / (BN / TN);   // 0..15

    float acc[TM][TN];
#pragma unroll
    for (int i = 0; i < TM; i++)
#pragma unroll
        for (int j = 0; j < TN; j++) acc[i][j] = 0.0f;

    for (int k0 = 0; k0 < K; k0 += BK) {
        // Load A tile (BM x BK) -> As transposed.  512 float4 total, 2/thread.
#pragma unroll
        for (int i = 0; i < 2; i++) {
            int idx = tid + i * 256;            // 0..511
            int r   = idx >> 2;                 // /(BK/4)=4 -> 0..127
            int c4  = idx & 3;
            float4 a = *(const float4*)(A + (size_t)(brow + r) * K + k0 + c4 * 4);
            As[c4 * 4 + 0][r] = a.x;
            As[c4 * 4 + 1][r] = a.y;
            As[c4 * 4 + 2][r] = a.z;
            As[c4 * 4 + 3][r] = a.w;
        }
        // Load B tile (BK x BN). 512 float4 total, 2/thread.
#pragma unroll
        for (int i = 0; i < 2; i++) {
            int idx = tid + i * 256;
            int r   = idx >> 5;                 // /(BN/4)=32 -> 0..15
            int c4  = idx & 31;
            *(float4*)(&Bs[r][c4 * 4]) =
                *(const float4*)(B + (size_t)(k0 + r) * N + bcol + c4 * 4);
        }
        __syncthreads();

#pragma unroll
        for (int k = 0; k < BK; k++) {
            float a[TM], b[TN];
#pragma unroll
            for (int i = 0; i < TM; i++) a[i] = As[k][ty * TM + i];
#pragma unroll
            for (int j = 0; j < TN; j++) b[j] = Bs[k][tx * TN + j];
#pragma unroll
            for (int i = 0; i < TM; i++)
#pragma unroll
                for (int j = 0; j < TN; j++)
                    acc[i][j] += a[i] * b[j];
        }
        __syncthreads();
    }

#pragma unroll
    for (int i = 0; i < TM; i++) {
#pragma unroll
        for (int j = 0; j < TN; j += 4) {
            float4 o = make_float4(acc[i][j], acc[i][j+1], acc[i][j+2], acc[i][j+3]);
            *(float4*)(C + (size_t)(brow + ty * TM + i) * N + bcol + tx * TN + j) = o;
        }
    }
}

// ---------------- feature map: out[bl,h,m] = relu(ratio * x[bl,h,:]·proj[m,:]) + eps
// grid = BL blocks, 128 threads (thread = m)
__global__ __launch_bounds__(128)
void feature_kernel(const float* __restrict__ x, const float* __restrict__ proj,
                    float* __restrict__ out)
{
    __shared__ float xs[HH * DH];     // 1024 floats
    const int bl = blockIdx.x;
    const float* xp = x + (size_t)bl * HH * DH;
    for (int i = threadIdx.x; i < HH * DH; i += 128) xs[i] = xp[i];
    __syncthreads();

    const int m = threadIdx.x;
    float pr[DH];
#pragma unroll
    for (int d = 0; d < DH; d++) pr[d] = proj[m * DH + d];

    const float ratio = 0.08838834764831845f;   // 1/sqrt(128)
    float* op = out + (size_t)bl * HH * MM;
#pragma unroll 2
    for (int h = 0; h < HH; h++) {
        float s = 0.0f;
#pragma unroll
        for (int d = 0; d < DH; d++) s += xs[h * DH + d] * pr[d];
        s = fmaxf(ratio * s, 0.0f) + EPS;
        op[h * MM + m] = s;
    }
}

// ---------------- kvs partial: part[bh,chunk,m,0:64] = sum_l kp*v ; col 64 = sum_l kp
// grid = (LSPLIT, B*H), 256 threads. Each chunk covers L/LSPLIT = 256 rows.
__global__ __launch_bounds__(256)
void kvs_partial_kernel(const float* __restrict__ kp, const float* __restrict__ v,
                        float* __restrict__ part)
{
    const int TL = 32;
    __shared__ float kps[TL][MM];     // 16 KB
    __shared__ float vs [TL][DH];     // 8 KB

    const int bh    = blockIdx.y;               // 0..63
    const int b     = bh / HH;
    const int h     = bh % HH;
    const int chunk = blockIdx.x;
    const int l0    = chunk * (LL / LSPLIT);    // *256
    const int tid   = threadIdx.x;
    const int tm    = tid / 16;                 // 0..15 -> 8 m's
    const int td    = tid % 16;                 // 0..15 -> 4 d's

    float acc[8][4];
#pragma unroll
    for (int i = 0; i < 8; i++)
#pragma unroll
        for (int j = 0; j < 4; j++) acc[i][j] = 0.0f;
    float accs[8] = {0,0,0,0,0,0,0,0};

    for (int lt = 0; lt < LL / LSPLIT; lt += TL) {
        // kp tile: TL x 128 = 1024 float4, 4/thread
#pragma unroll
        for (int i = 0; i < 4; i++) {
            int idx = tid + i * 256;
            int r   = idx >> 5;                 // /32
            int c4  = idx & 31;
            size_t g = (((size_t)b * LL + l0 + lt + r) * HH + h) * MM + c4 * 4;
            *(float4*)(&kps[r][c4 * 4]) = *(const float4*)(kp + g);
        }
        // v tile: TL x 64 = 512 float4, 2/thread
#pragma unroll
        for (int i = 0; i < 2; i++) {
            int idx = tid + i * 256;
            int r   = idx >> 4;                 // /16
            int c4  = idx & 15;
            size_t g = (((size_t)b * LL + l0 + lt + r) * HH + h) * DH + c4 * 4;
            *(float4*)(&vs[r][c4 * 4]) = *(const float4*)(v + g);
        }
        __syncthreads();

#pragma unroll
        for (int l = 0; l < TL; l++) {
            float a[8], bb[4];
#pragma unroll
            for (int i = 0; i < 8; i++) a[i] = kps[l][tm * 8 + i];
#pragma unroll
            for (int j = 0; j < 4; j++) bb[j] = vs[l][td * 4 + j];
#pragma unroll
            for (int i = 0; i < 8; i++)
#pragma unroll
                for (int j = 0; j < 4; j++)
                    acc[i][j] += a[i] * bb[j];
            if (td == 0) {
#pragma unroll
                for (int i = 0; i < 8; i++) accs[i] += a[i];
            }
        }
        __syncthreads();
    }

    float* p = part + ((size_t)bh * LSPLIT + chunk) * MM * 65;
#pragma unroll
    for (int i = 0; i < 8; i++)
#pragma unroll
        for (int j = 0; j < 4; j++)
            p[(tm * 8 + i) * 65 + td * 4 + j] = acc[i][j];
    if (td == 0) {
#pragma unroll
        for (int i = 0; i < 8; i++) p[(tm * 8 + i) * 65 + 64] = accs[i];
    }
}

// ---------------- kvs reduce over LSPLIT chunks ------------------------------
__global__ void kvs_reduce_kernel(const float* __restrict__ part, float* __restrict__ kvs)
{
    int idx = blockIdx.x * blockDim.x + threadIdx.x;
    const int TOT = BB * HH * MM * 65;
    if (idx >= TOT) return;
    int bh  = idx / (MM * 65);
    int rem = idx % (MM * 65);
    float s = 0.0f;
#pragma unroll
    for (int c = 0; c < LSPLIT; c++)
        s += part[((size_t)bh * LSPLIT + c) * MM * 65 + rem];
    kvs[idx] = s;
}

// ---------------- attention combine: att[bl, h*64+d] = (qp·kvs)/(qp·ks_sum) --
// grid = BL blocks, 1024 threads (thread = h*64+d)
__global__ __launch_bounds__(1024)
void attn_kernel(const float* __restrict__ qp, const float* __restrict__ kvs,
                 float* __restrict__ att)
{
    __shared__ float qs[HH * MM];     // 2048 floats
    __shared__ float dens[HH];

    const int bl = blockIdx.x;
    const int b  = bl / LL;
    const int tid = threadIdx.x;

    const float* qpp = qp + (size_t)bl * HH * MM;
    for (int i = tid; i < HH * MM; i += 1024) qs[i] = qpp[i];
    __syncthreads();

    if (tid < HH) {
        const float* kv = kvs + ((size_t)(b * HH + tid) * MM) * 65 + 64;
        float s = 0.0f;
#pragma unroll 4
        for (int m = 0; m < MM; m++) s += qs[tid * MM + m] * kv[m * 65];
        dens[tid] = s;
    }
    __syncthreads();

    const int h = tid >> 6, d = tid & 63;
    const float* kv = kvs + ((size_t)(b * HH + h) * MM) * 65 + d;
    const float* q  = qs + h * MM;
    float s = 0.0f;
#pragma unroll 8
    for (int m = 0; m < MM; m++) s += q[m] * kv[m * 65];
    att[(size_t)bl * (HH * DH) + tid] = s / dens[h];
}

// ---------------- launch ------------------------------------------------------
extern "C" void kernel_launch(void* const* d_in, const int* in_sizes, int n_in,
                              void* d_out, int out_size)
{
    const float* qin  = (const float*)d_in[0];
    const float* sin_ = (const float*)d_in[1];
    const float* Wq   = (const float*)d_in[2];
    const float* Wk   = (const float*)d_in[3];
    const float* Wv   = (const float*)d_in[4];
    const float* Wo   = (const float*)d_in[5];
    const float* proj = (const float*)d_in[6];
    float* out = (float*)d_out;

    float *pq, *pk, *pv, *pqp, *pkp, *ppart, *pkvs;
    cudaGetSymbolAddress((void**)&pq,    g_q);
    cudaGetSymbolAddress((void**)&pk,    g_k);
    cudaGetSymbolAddress((void**)&pv,    g_v);
    cudaGetSymbolAddress((void**)&pqp,   g_qp);
    cudaGetSymbolAddress((void**)&pkp,   g_kp);
    cudaGetSymbolAddress((void**)&ppart, g_part);
    cudaGetSymbolAddress((void**)&pkvs,  g_kvs);

    dim3 ggrid(HID / 128, BL / 128);   // (8, 128)

    sgemm_kernel<<<ggrid, 256>>>(qin,  Wq, pq, BL, HID, HID);
    sgemm_kernel<<<ggrid, 256>>>(sin_, Wk, pk, BL, HID, HID);
    sgemm_kernel<<<ggrid, 256>>>(sin_, Wv, pv, BL, HID, HID);

    feature_kernel<<<BL, 128>>>(pq, proj, pqp);
    feature_kernel<<<BL, 128>>>(pk, proj, pkp);

    kvs_partial_kernel<<<dim3(LSPLIT, BB * HH), 256>>>(pkp, pv, ppart);
    {
        const int TOT = BB * HH * MM * 65;
        kvs_reduce_kernel<<<(TOT + 255) / 256, 256>>>(ppart, pkvs);
    }

    // att reuses g_q (q no longer needed after qp computed)
    attn_kernel<<<BL, 1024>>>(pqp, pkvs, pq);

    sgemm_kernel<<<ggrid, 256>>>(pq, Wo, out, BL, HID, HID);
}

// round 8
// speedup vs baseline: 1.5829x; 1.5829x over previous
#include <cuda_runtime.h>
#include <cuda_bf16.h>
#include <cstdint>

// Problem constants
#define BB   4
#define LL   4096
#define HID  1024
#define HH   16
#define DH   64
#define MM   128
#define BL   (BB*LL)          // 16384
#define EPS  1e-3f
#define KDIM 1024
#define NQP  2048             // H*M
#define NCHUNK 48             // 3 splits * (1024/64)
#define RATIO 0.08838834764831845f

// ---------------- scratch (static device globals; no allocation) -------------
__device__ __nv_bfloat16 g_qin_h[(size_t)BL*KDIM], g_qin_l[(size_t)BL*KDIM];
__device__ __nv_bfloat16 g_sin_h[(size_t)BL*KDIM], g_sin_l[(size_t)BL*KDIM];
__device__ __nv_bfloat16 g_WqPt_h[(size_t)NQP*KDIM], g_WqPt_l[(size_t)NQP*KDIM];
__device__ __nv_bfloat16 g_WkPt_h[(size_t)NQP*KDIM], g_WkPt_l[(size_t)NQP*KDIM];
__device__ __nv_bfloat16 g_Wvt_h[(size_t)HID*KDIM],  g_Wvt_l[(size_t)HID*KDIM];
__device__ __nv_bfloat16 g_Wot_h[(size_t)HID*KDIM],  g_Wot_l[(size_t)HID*KDIM];
__device__ float g_qp[(size_t)BL*NQP];      // 128 MB
__device__ float g_kp[(size_t)BL*NQP];      // 128 MB
__device__ float g_v [(size_t)BL*HID];      // 64 MB
__device__ __nv_bfloat16 g_att_h[(size_t)BL*HID], g_att_l[(size_t)BL*HID];
#define LSPLIT 16
__device__ float g_part[(size_t)BB*HH*LSPLIT*MM*65];
__device__ float g_kvs [(size_t)BB*HH*MM*65];

// ---------------- PTX helpers ------------------------------------------------
__device__ __forceinline__ uint32_t smem_u32(const void* p){
    return (uint32_t)__cvta_generic_to_shared(p);
}
#define SW128(o) ((o) ^ (((o) >> 3) & 0x70))

#define CP_ASYNC16(s, g) \
    asm volatile("cp.async.cg.shared.global [%0], [%1], 16;\n" :: "r"(s), "l"(g) : "memory")
#define CP_COMMIT() asm volatile("cp.async.commit_group;\n" ::: "memory")
template<int N> __device__ __forceinline__ void cp_wait(){
    asm volatile("cp.async.wait_group %0;\n" :: "n"(N) : "memory");
}

__device__ __forceinline__ void ldsm_x4(uint32_t& r0, uint32_t& r1, uint32_t& r2,
                                        uint32_t& r3, uint32_t addr){
    asm volatile("ldmatrix.sync.aligned.m8n8.x4.shared.b16 {%0,%1,%2,%3}, [%4];"
                 : "=r"(r0), "=r"(r1), "=r"(r2), "=r"(r3) : "r"(addr));
}
__device__ __forceinline__ void mma16816(float* c, const uint32_t* a, const uint32_t* b){
    asm volatile("mma.sync.aligned.m16n8k16.row.col.f32.bf16.bf16.f32 "
                 "{%0,%1,%2,%3}, {%4,%5,%6,%7}, {%8,%9}, {%0,%1,%2,%3};"
                 : "+f"(c[0]), "+f"(c[1]), "+f"(c[2]), "+f"(c[3])
                 : "r"(a[0]), "r"(a[1]), "r"(a[2]), "r"(a[3]), "r"(b[0]), "r"(b[1]));
}

// ---------------- HMMA bf16-split GEMM ---------------------------------------
// C[M,Ntot] = (Ah+Al)[M,1024] @ (Bh+Bl)^T   (Bt stored row-major [Ntot,1024])
// computed as AhBh + AhBl + AlBh.  CTA tile 128x128, BK=64, 3-stage cp.async.
// 256 threads = 8 warps (warp_m 0..3 -> 32 rows, warp_n 0..1 -> 64 cols).
// MODE 0: C = val ; MODE 1: C = relu(RATIO*val)+EPS
#define GEMM_SMEM (3*32768)

template<int MODE>
__global__ __launch_bounds__(256)
void gemm_kernel(const __nv_bfloat16* __restrict__ Ah, const __nv_bfloat16* __restrict__ Al,
                 const __nv_bfloat16* __restrict__ Bh, const __nv_bfloat16* __restrict__ Bl,
                 float* __restrict__ C, int Ntot)
{
    extern __shared__ char dsm_raw[];
    const uint32_t dsm = smem_u32(dsm_raw);
    const int tid  = threadIdx.x;
    const int wid  = tid >> 5;
    const int lane = tid & 31;
    const int warp_m = wid & 3;      // 0..3 -> 32-row slab
    const int warp_n = wid >> 2;     // 0..1 -> 64-col slab
    const int tile_m = blockIdx.y * 128;
    const int tile_n = blockIdx.x * 128;

    float acc[2][8][4];
#pragma unroll
    for (int i = 0; i < 2; i++)
#pragma unroll
        for (int j = 0; j < 8; j++)
#pragma unroll
            for (int t = 0; t < 4; t++) acc[i][j][t] = 0.0f;

    // ---- loader: each chunk = A 128x64bf16 (16KB) + B 128x64bf16 (16KB)
    auto load_chunk = [&](int c, int stage){
        const int s  = c >> 4;              // split id 0..2
        const int kk = (c & 15) << 6;       // k0 (elements)
        const __nv_bfloat16* Ap = (s < 2) ? Ah : Al;
        const __nv_bfloat16* Bp = (s == 1) ? Bl : Bh;
        const uint32_t sA = dsm + stage * 32768;
        const uint32_t sB = sA + 16384;
#pragma unroll
        for (int i = 0; i < 4; i++){
            int idx = tid + i * 256;        // 0..1023
            int row = idx >> 3;             // 0..127
            int c16 = idx & 7;              // 16B slot within 128B row
            uint32_t so = SW128((uint32_t)(row * 128 + c16 * 16));
            CP_ASYNC16(sA + so, Ap + (size_t)(tile_m + row) * KDIM + kk + c16 * 8);
            CP_ASYNC16(sB + so, Bp + (size_t)(tile_n + row) * KDIM + kk + c16 * 8);
        }
        CP_COMMIT();
    };

    load_chunk(0, 0);
    load_chunk(1, 1);

    // ldmatrix per-lane address components (row within tile, 16B column slot)
    const int a_r  = (lane & 7) + ((lane >> 3) & 1) * 8;   // m-row offset 0..15
    const int a_c  = (lane >> 4) * 16;                     // +0 / +16 bytes (k half)
    const int b_r  = (lane & 7) + ((lane >> 4) & 1) * 8;   // n-row offset 0..15
    const int b_c  = ((lane >> 3) & 1) * 16;               // +0 / +16 bytes (k half)

    for (int c = 0; c < NCHUNK; c++){
        const int st = c % 3;
        if (c + 2 < NCHUNK) load_chunk(c + 2, (c + 2) % 3);
        if (c + 2 < NCHUNK)      cp_wait<2>();
        else if (c + 1 < NCHUNK) cp_wait<1>();
        else                     cp_wait<0>();
        __syncthreads();

        const uint32_t sA = dsm + st * 32768;
        const uint32_t sB = sA + 16384;
#pragma unroll
        for (int ks = 0; ks < 4; ks++){     // 4 x k16
            uint32_t afr[2][4];
#pragma unroll
            for (int mt = 0; mt < 2; mt++){
                int row = warp_m * 32 + mt * 16 + a_r;
                uint32_t addr = sA + SW128((uint32_t)(row * 128 + ks * 32 + a_c));
                ldsm_x4(afr[mt][0], afr[mt][1], afr[mt][2], afr[mt][3], addr);
            }
            uint32_t bfr[4][4];
#pragma unroll
            for (int np = 0; np < 4; np++){ // each covers 2 n-tiles
                int row = warp_n * 64 + np * 16 + b_r;
                uint32_t addr = sB + SW128((uint32_t)(row * 128 + ks * 32 + b_c));
                ldsm_x4(bfr[np][0], bfr[np][1], bfr[np][2], bfr[np][3], addr);
            }
#pragma unroll
            for (int mt = 0; mt < 2; mt++)
#pragma unroll
                for (int np = 0; np < 4; np++){
                    mma16816(acc[mt][np*2+0], afr[mt], &bfr[np][0]);
                    mma16816(acc[mt][np*2+1], afr[mt], &bfr[np][2]);
                }
        }
        __syncthreads();
    }

    // ---- epilogue: c frag lane mapping (m16n8): rows g, g+8 ; cols t*2, t*2+1
    const int g  = lane >> 2;
    const int t4 = lane & 3;
#pragma unroll
    for (int mt = 0; mt < 2; mt++){
        int row0 = tile_m + warp_m * 32 + mt * 16 + g;
#pragma unroll
        for (int nt = 0; nt < 8; nt++){
            int col = tile_n + warp_n * 64 + nt * 8 + t4 * 2;
            float v0 = acc[mt][nt][0], v1 = acc[mt][nt][1];
            float v2 = acc[mt][nt][2], v3 = acc[mt][nt][3];
            if (MODE == 1){
                v0 = fmaxf(v0 * RATIO, 0.f) + EPS;
                v1 = fmaxf(v1 * RATIO, 0.f) + EPS;
                v2 = fmaxf(v2 * RATIO, 0.f) + EPS;
                v3 = fmaxf(v3 * RATIO, 0.f) + EPS;
            }
            *(float2*)(C + (size_t)row0       * Ntot + col) = make_float2(v0, v1);
            *(float2*)(C + (size_t)(row0 + 8) * Ntot + col) = make_float2(v2, v3);
        }
    }
}

// ---------------- prep: fp32 -> (bf16 hi, bf16 lo) ---------------------------
__global__ void split_kernel(const float* __restrict__ x, __nv_bfloat16* __restrict__ hi,
                             __nv_bfloat16* __restrict__ lo, int n4)
{
    int i = blockIdx.x * blockDim.x + threadIdx.x;
    if (i >= n4) return;
    float4 v = ((const float4*)x)[i];
    __nv_bfloat16 h0 = __float2bfloat16(v.x), h1 = __float2bfloat16(v.y);
    __nv_bfloat16 h2 = __float2bfloat16(v.z), h3 = __float2bfloat16(v.w);
    __nv_bfloat16 l0 = __float2bfloat16(v.x - __bfloat162float(h0));
    __nv_bfloat16 l1 = __float2bfloat16(v.y - __bfloat162float(h1));
    __nv_bfloat16 l2 = __float2bfloat16(v.z - __bfloat162float(h2));
    __nv_bfloat16 l3 = __float2bfloat16(v.w - __bfloat162float(h3));
    ((__nv_bfloat162*)hi)[i*2+0] = __nv_bfloat162(h0, h1);
    ((__nv_bfloat162*)hi)[i*2+1] = __nv_bfloat162(h2, h3);
    ((__nv_bfloat162*)lo)[i*2+0] = __nv_bfloat162(l0, l1);
    ((__nv_bfloat162*)lo)[i*2+1] = __nv_bfloat162(l2, l3);
}

// ---------------- prep: fold proj into Wq/Wk, transposed + split -------------
// out row n = h*128+m:  WPt[n][k] = sum_d W[k,h,d] * proj[m,d]
__global__ __launch_bounds__(256)
void fold_kernel(const float* __restrict__ W, const float* __restrict__ proj,
                 __nv_bfloat16* __restrict__ th, __nv_bfloat16* __restrict__ tl)
{
    __shared__ float ps[DH];
    const int n = blockIdx.x;
    const int h = n >> 7, m = n & 127;
    for (int d = threadIdx.x; d < DH; d += 256) ps[d] = proj[m*DH + d];
    __syncthreads();
    for (int k = threadIdx.x; k < KDIM; k += 256){
        const float* wp = W + ((size_t)k*HH + h)*DH;
        float s = 0.f;
#pragma unroll
        for (int d = 0; d < DH; d++) s += wp[d] * ps[d];
        __nv_bfloat16 hh = __float2bfloat16(s);
        __nv_bfloat16 ll = __float2bfloat16(s - __bfloat162float(hh));
        th[(size_t)n*KDIM + k] = hh;
        tl[(size_t)n*KDIM + k] = ll;
    }
}

// ---------------- prep: transpose [1024,1024] + split ------------------------
__global__ void transpose_split_kernel(const float* __restrict__ W,
                                       __nv_bfloat16* __restrict__ th,
                                       __nv_bfloat16* __restrict__ tl)
{
    __shared__ float t[32][33];
    const int bx = blockIdx.x * 32, by = blockIdx.y * 32;
    const int tx = threadIdx.x, ty0 = threadIdx.y;
#pragma unroll
    for (int ty = ty0; ty < 32; ty += 8)
        t[ty][tx] = W[(size_t)(by + ty)*HID + bx + tx];
    __syncthreads();
#pragma unroll
    for (int ty = ty0; ty < 32; ty += 8){
        float v = t[tx][ty];
        __nv_bfloat16 hh = __float2bfloat16(v);
        __nv_bfloat16 ll = __float2bfloat16(v - __bfloat162float(hh));
        th[(size_t)(bx + ty)*KDIM + by + tx] = hh;
        tl[(size_t)(bx + ty)*KDIM + by + tx] = ll;
    }
}

// ---------------- kvs partial / reduce ---------------------------------------
__global__ __launch_bounds__(256)
void kvs_partial_kernel(const float* __restrict__ kp, const float* __restrict__ v,
                        float* __restrict__ part)
{
    const int TL = 32;
    __shared__ float kps[TL][MM];
    __shared__ float vs [TL][DH];
    const int bh    = blockIdx.y;
    const int b     = bh / HH;
    const int h     = bh % HH;
    const int chunk = blockIdx.x;
    const int l0    = chunk * (LL / LSPLIT);
    const int tid   = threadIdx.x;
    const int tm    = tid / 16;
    const int td    = tid % 16;

    float acc[8][4];
#pragma unroll
    for (int i = 0; i < 8; i++)
#pragma unroll
        for (int j = 0; j < 4; j++) acc[i][j] = 0.0f;
    float accs[8] = {0,0,0,0,0,0,0,0};

    for (int lt = 0; lt < LL / LSPLIT; lt += TL) {
#pragma unroll
        for (int i = 0; i < 4; i++) {
            int idx = tid + i * 256;
            int r = idx >> 5, c4 = idx & 31;
            size_t g = (((size_t)b * LL + l0 + lt + r) * HH + h) * MM + c4 * 4;
            *(float4*)(&kps[r][c4 * 4]) = *(const float4*)(kp + g);
        }
#pragma unroll
        for (int i = 0; i < 2; i++) {
            int idx = tid + i * 256;
            int r = idx >> 4, c4 = idx & 15;
            size_t g = (((size_t)b * LL + l0 + lt + r) * HH + h) * DH + c4 * 4;
            *(float4*)(&vs[r][c4 * 4]) = *(const float4*)(v + g);
        }
        __syncthreads();
#pragma unroll
        for (int l = 0; l < TL; l++) {
            float a[8], bb[4];
#pragma unroll
            for (int i = 0; i < 8; i++) a[i] = kps[l][tm * 8 + i];
#pragma unroll
            for (int j = 0; j < 4; j++) bb[j] = vs[l][td * 4 + j];
#pragma unroll
            for (int i = 0; i < 8; i++)
#pragma unroll
                for (int j = 0; j < 4; j++)
                    acc[i][j] += a[i] * bb[j];
            if (td == 0) {
#pragma unroll
                for (int i = 0; i < 8; i++) accs[i] += a[i];
            }
        }
        __syncthreads();
    }
    float* p = part + ((size_t)bh * LSPLIT + chunk) * MM * 65;
#pragma unroll
    for (int i = 0; i < 8; i++)
#pragma unroll
        for (int j = 0; j < 4; j++)
            p[(tm * 8 + i) * 65 + td * 4 + j] = acc[i][j];
    if (td == 0) {
#pragma unroll
        for (int i = 0; i < 8; i++) p[(tm * 8 + i) * 65 + 64] = accs[i];
    }
}

__global__ void kvs_reduce_kernel(const float* __restrict__ part, float* __restrict__ kvs)
{
    int idx = blockIdx.x * blockDim.x + threadIdx.x;
    const int TOT = BB * HH * MM * 65;
    if (idx >= TOT) return;
    int bh = idx / (MM * 65), rem = idx % (MM * 65);
    float s = 0.0f;
#pragma unroll
    for (int c = 0; c < LSPLIT; c++)
        s += part[((size_t)bh * LSPLIT + c) * MM * 65 + rem];
    kvs[idx] = s;
}

// ---------------- attention combine, epilogue writes split bf16 --------------
__global__ __launch_bounds__(1024)
void attn_kernel(const float* __restrict__ qp, const float* __restrict__ kvs,
                 __nv_bfloat16* __restrict__ att_h, __nv_bfloat16* __restrict__ att_l)
{
    __shared__ float qs[HH * MM];
    __shared__ float dens[HH];
    const int bl = blockIdx.x;
    const int b  = bl / LL;
    const int tid = threadIdx.x;

    const float* qpp = qp + (size_t)bl * HH * MM;
    for (int i = tid; i < HH * MM; i += 1024) qs[i] = qpp[i];
    __syncthreads();

    if (tid < HH) {
        const float* kv = kvs + ((size_t)(b * HH + tid) * MM) * 65 + 64;
        float s = 0.0f;
#pragma unroll 4
        for (int m = 0; m < MM; m++) s += qs[tid * MM + m] * kv[m * 65];
        dens[tid] = s;
    }
    __syncthreads();

    const int h = tid >> 6, d = tid & 63;
    const float* kv = kvs + ((size_t)(b * HH + h) * MM) * 65 + d;
    const float* q  = qs + h * MM;
    float s = 0.0f;
#pragma unroll 8
    for (int m = 0; m < MM; m++) s += q[m] * kv[m * 65];
    float val = s / dens[h];
    __nv_bfloat16 hh = __float2bfloat16(val);
    __nv_bfloat16 ll = __float2bfloat16(val - __bfloat162float(hh));
    att_h[(size_t)bl * HID + tid] = hh;
    att_l[(size_t)bl * HID + tid] = ll;
}

// ---------------- launch ------------------------------------------------------
extern "C" void kernel_launch(void* const* d_in, const int* in_sizes, int n_in,
                              void* d_out, int out_size)
{
    const float* qin  = (const float*)d_in[0];
    const float* sin_ = (const float*)d_in[1];
    const float* Wq   = (const float*)d_in[2];
    const float* Wk   = (const float*)d_in[3];
    const float* Wv   = (const float*)d_in[4];
    const float* Wo   = (const float*)d_in[5];
    const float* proj = (const float*)d_in[6];
    float* out = (float*)d_out;

    __nv_bfloat16 *pqin_h,*pqin_l,*psin_h,*psin_l;
    __nv_bfloat16 *pWqPt_h,*pWqPt_l,*pWkPt_h,*pWkPt_l,*pWvt_h,*pWvt_l,*pWot_h,*pWot_l;
    __nv_bfloat16 *patt_h,*patt_l;
    float *pqp,*pkp,*pv,*ppart,*pkvs;
    cudaGetSymbolAddress((void**)&pqin_h, g_qin_h);  cudaGetSymbolAddress((void**)&pqin_l, g_qin_l);
    cudaGetSymbolAddress((void**)&psin_h, g_sin_h);  cudaGetSymbolAddress((void**)&psin_l, g_sin_l);
    cudaGetSymbolAddress((void**)&pWqPt_h, g_WqPt_h); cudaGetSymbolAddress((void**)&pWqPt_l, g_WqPt_l);
    cudaGetSymbolAddress((void**)&pWkPt_h, g_WkPt_h); cudaGetSymbolAddress((void**)&pWkPt_l, g_WkPt_l);
    cudaGetSymbolAddress((void**)&pWvt_h, g_Wvt_h);  cudaGetSymbolAddress((void**)&pWvt_l, g_Wvt_l);
    cudaGetSymbolAddress((void**)&pWot_h, g_Wot_h);  cudaGetSymbolAddress((void**)&pWot_l, g_Wot_l);
    cudaGetSymbolAddress((void**)&patt_h, g_att_h);  cudaGetSymbolAddress((void**)&patt_l, g_att_l);
    cudaGetSymbolAddress((void**)&pqp, g_qp);        cudaGetSymbolAddress((void**)&pkp, g_kp);
    cudaGetSymbolAddress((void**)&pv, g_v);
    cudaGetSymbolAddress((void**)&ppart, g_part);    cudaGetSymbolAddress((void**)&pkvs, g_kvs);

    cudaFuncSetAttribute(gemm_kernel<0>, cudaFuncAttributeMaxDynamicSharedMemorySize, GEMM_SMEM);
    cudaFuncSetAttribute(gemm_kernel<1>, cudaFuncAttributeMaxDynamicSharedMemorySize, GEMM_SMEM);

    // input splits
    {
        int n4 = BL * KDIM / 4;
        split_kernel<<<(n4 + 255)/256, 256>>>(qin,  pqin_h, pqin_l, n4);
        split_kernel<<<(n4 + 255)/256, 256>>>(sin_, psin_h, psin_l, n4);
    }
    // weight prep
    fold_kernel<<<NQP, 256>>>(Wq, proj, pWqPt_h, pWqPt_l);
    fold_kernel<<<NQP, 256>>>(Wk, proj, pWkPt_h, pWkPt_l);
    transpose_split_kernel<<<dim3(32,32), dim3(32,8)>>>(Wv, pWvt_h, pWvt_l);
    transpose_split_kernel<<<dim3(32,32), dim3(32,8)>>>(Wo, pWot_h, pWot_l);

    // qp / kp / v via HMMA split-bf16 GEMMs
    gemm_kernel<1><<<dim3(NQP/128, BL/128), 256, GEMM_SMEM>>>(pqin_h, pqin_l, pWqPt_h, pWqPt_l, pqp, NQP);
    gemm_kernel<1><<<dim3(NQP/128, BL/128), 256, GEMM_SMEM>>>(psin_h, psin_l, pWkPt_h, pWkPt_l, pkp, NQP);
    gemm_kernel<0><<<dim3(HID/128, BL/128), 256, GEMM_SMEM>>>(psin_h, psin_l, pWvt_h, pWvt_l, pv, HID);

    // FAVOR+ aggregation
    kvs_partial_kernel<<<dim3(LSPLIT, BB*HH), 256>>>(pkp, pv, ppart);
    {
        const int TOT = BB * HH * MM * 65;
        kvs_reduce_kernel<<<(TOT + 255)/256, 256>>>(ppart, pkvs);
    }
    attn_kernel<<<BL, 1024>>>(pqp, pkvs, patt_h, patt_l);

    // output projection
    gemm_kernel<0><<<dim3(HID/128, BL/128), 256, GEMM_SMEM>>>(patt_h, patt_l, pWot_h, pWot_l, out, HID);
}